// round 4
// baseline (speedup 1.0000x reference)
#include <cuda_runtime.h>

#define D 96
#define NMAX 50000
#define EMAX 800000
#define SCAN_B 512
#define NSCANBLK ((NMAX + SCAN_B - 1) / SCAN_B)   // 98

// ---------------- scratch (static device globals; no allocation) ----------
__device__ int   g_counts[NMAX];
__device__ int   g_rowptr[NMAX + 1];
__device__ int   g_cursor[NMAX];
__device__ float g_dinv[NMAX];
__device__ int2  g_adj[EMAX];                 // {src, bitcast(norm)}
__device__ float g_h1[(size_t)NMAX * D];      // ping buffer
__device__ float g_h2[(size_t)NMAX * D];      // pong buffer
__device__ int   g_blockSums[NSCANBLK + 2];

// ---------------- graph preprocessing -------------------------------------
__global__ void k_zero_counts(int n) {
    int i = blockIdx.x * blockDim.x + threadIdx.x;
    if (i < n) g_counts[i] = 0;
}

// edge_index is int32 (JAX x64 disabled downcasts int64 -> int32)
__global__ void k_hist(const int* __restrict__ ei, int E) {
    int e = blockIdx.x * blockDim.x + threadIdx.x;
    if (e < E) {
        int d = ei[E + e];
        atomicAdd(&g_counts[d], 1);
    }
}

__global__ void k_dinv(int n) {
    int i = blockIdx.x * blockDim.x + threadIdx.x;
    if (i < n) g_dinv[i] = rsqrtf((float)(g_counts[i] + 1)); // +1 self loop
}

// block-local exclusive scan of counts -> g_rowptr, block totals -> g_blockSums
__global__ void k_scan1(int n) {
    __shared__ int s[SCAN_B];
    int i = blockIdx.x * SCAN_B + threadIdx.x;
    int v = (i < n) ? g_counts[i] : 0;
    s[threadIdx.x] = v;
    __syncthreads();
    for (int off = 1; off < SCAN_B; off <<= 1) {
        int t = (threadIdx.x >= off) ? s[threadIdx.x - off] : 0;
        __syncthreads();
        s[threadIdx.x] += t;
        __syncthreads();
    }
    if (i < n) g_rowptr[i] = s[threadIdx.x] - v; // exclusive
    if (threadIdx.x == SCAN_B - 1) g_blockSums[blockIdx.x] = s[SCAN_B - 1];
}

// parallel scan of the (<=128) block sums
__global__ void k_scan2(int nb, int n) {
    __shared__ int s[128];
    int t = threadIdx.x;
    int v = (t < nb) ? g_blockSums[t] : 0;
    s[t] = v;
    __syncthreads();
    for (int off = 1; off < 128; off <<= 1) {
        int u = (t >= off) ? s[t - off] : 0;
        __syncthreads();
        s[t] += u;
        __syncthreads();
    }
    if (t < nb) g_blockSums[t] = s[t] - v;   // exclusive
    if (t == 127) g_rowptr[n] = s[127];      // total = E
}

__global__ void k_scan3(int n) {
    int i = blockIdx.x * SCAN_B + threadIdx.x;
    if (i < n) {
        int v = g_rowptr[i] + g_blockSums[blockIdx.x];
        g_rowptr[i] = v;
        g_cursor[i] = v;
    }
}

__global__ void k_scatter(const int* __restrict__ ei, int E) {
    int e = blockIdx.x * blockDim.x + threadIdx.x;
    if (e < E) {
        int s = ei[e];
        int d = ei[E + e];
        int pos = atomicAdd(&g_cursor[d], 1);
        float norm = g_dinv[s] * g_dinv[d];
        g_adj[pos] = make_int2(s, __float_as_int(norm));
    }
}

// ---------------- dense GEMM: Y[N,96] = X[N,96] @ W[96,96] -----------------
// block: (96,2) = 192 threads, TM=32 nodes per block.
// src_sel: 0 = external X pointer, 1 = g_h2.  Output always g_h1.
#define TM 32
__global__ __launch_bounds__(192) void k_gemm(const float* __restrict__ Xext,
                                              const float* __restrict__ W,
                                              int n, int src_sel) {
    __shared__ __align__(16) float Ws[96 * 96];
    __shared__ __align__(16) float Xs[TM][96];
    const float* X = (src_sel == 0) ? Xext : (const float*)g_h2;
    float* Y = (float*)g_h1;

    int tx = threadIdx.x;               // output feature d (0..95)
    int ty = threadIdx.y;               // 0..1
    int tid = ty * 96 + tx;

    for (int i = tid; i < 96 * 96; i += 192) Ws[i] = W[i];

    int n0 = blockIdx.x * TM;
    int rows = min(TM, n - n0);
    const float4* Xv = (const float4*)(X + (size_t)n0 * 96);
    float4* Xsv = (float4*)&Xs[0][0];
    int nv = rows * 24;                 // float4 count of valid data
    for (int i = tid; i < TM * 24; i += 192)
        Xsv[i] = (i < nv) ? Xv[i] : make_float4(0.f, 0.f, 0.f, 0.f);
    __syncthreads();

    float acc[16];
#pragma unroll
    for (int i = 0; i < 16; i++) acc[i] = 0.f;

    for (int k = 0; k < 96; k += 4) {
        float w0 = Ws[(k + 0) * 96 + tx];
        float w1 = Ws[(k + 1) * 96 + tx];
        float w2 = Ws[(k + 2) * 96 + tx];
        float w3 = Ws[(k + 3) * 96 + tx];
#pragma unroll
        for (int i = 0; i < 16; i++) {
            int m = ty + 2 * i;
            float4 xv = *(const float4*)&Xs[m][k];
            acc[i] = fmaf(xv.x, w0, acc[i]);
            acc[i] = fmaf(xv.y, w1, acc[i]);
            acc[i] = fmaf(xv.z, w2, acc[i]);
            acc[i] = fmaf(xv.w, w3, acc[i]);
        }
    }
#pragma unroll
    for (int i = 0; i < 16; i++) {
        int m = ty + 2 * i;
        int nn = n0 + m;
        if (nn < n) Y[(size_t)nn * 96 + tx] = acc[i];
    }
}

// ---------------- aggregation: one warp per node ---------------------------
// reads g_h1; writes g_h2 (dst_sel=0) or external out (dst_sel=1).
// out[n,f] = b[f] + sum_{incoming e} h[src_e,f]*norm_e + h[n,f]*dinv[n]^2
__global__ __launch_bounds__(256) void k_agg(const float* __restrict__ bias,
                                             const float* __restrict__ aptr,
                                             float* __restrict__ outExt,
                                             int n, int do_prelu, int dst_sel) {
    int warp = (blockIdx.x * blockDim.x + threadIdx.x) >> 5;
    int lane = threadIdx.x & 31;
    if (warp >= n) return;

    const float* h = (const float*)g_h1;
    float* out = (dst_sel == 0) ? (float*)g_h2 : outExt;

    int f0 = lane, f1 = lane + 32, f2 = lane + 64;
    float dn = g_dinv[warp];
    float dn2 = dn * dn;
    const float* hr = h + (size_t)warp * 96;
    float a0 = hr[f0] * dn2;
    float a1 = hr[f1] * dn2;
    float a2 = hr[f2] * dn2;

    int e = g_rowptr[warp];
    int end = g_rowptr[warp + 1];

    for (; e + 1 < end; e += 2) {
        int2 q0 = g_adj[e];
        int2 q1 = g_adj[e + 1];
        const float* r0 = h + (size_t)q0.x * 96;
        const float* r1 = h + (size_t)q1.x * 96;
        float n0 = __int_as_float(q0.y);
        float n1 = __int_as_float(q1.y);
        float v00 = r0[f0], v01 = r0[f1], v02 = r0[f2];
        float v10 = r1[f0], v11 = r1[f1], v12 = r1[f2];
        a0 = fmaf(v00, n0, a0); a1 = fmaf(v01, n0, a1); a2 = fmaf(v02, n0, a2);
        a0 = fmaf(v10, n1, a0); a1 = fmaf(v11, n1, a1); a2 = fmaf(v12, n1, a2);
    }
    if (e < end) {
        int2 q = g_adj[e];
        const float* r = h + (size_t)q.x * 96;
        float nn = __int_as_float(q.y);
        a0 = fmaf(r[f0], nn, a0);
        a1 = fmaf(r[f1], nn, a1);
        a2 = fmaf(r[f2], nn, a2);
    }

    a0 += bias[f0]; a1 += bias[f1]; a2 += bias[f2];
    if (do_prelu) {
        float a = aptr[0];
        a0 = (a0 > 0.f) ? a0 : a * a0;
        a1 = (a1 > 0.f) ? a1 : a * a1;
        a2 = (a2 > 0.f) ? a2 : a * a2;
    }
    float* o = out + (size_t)warp * 96;
    o[f0] = a0; o[f1] = a1; o[f2] = a2;
}

// ---------------- launch ---------------------------------------------------
extern "C" void kernel_launch(void* const* d_in, const int* in_sizes, int n_in,
                              void* d_out, int out_size) {
    const float* x  = (const float*)d_in[0];
    const int*   ei = (const int*)d_in[1];      // int32! (JAX x64 disabled)
    const float* W1 = (const float*)d_in[2];
    const float* b1 = (const float*)d_in[3];
    const float* a1 = (const float*)d_in[4];
    const float* W2 = (const float*)d_in[5];
    const float* b2 = (const float*)d_in[6];
    float*       out = (float*)d_out;

    int N = in_sizes[0] / D;
    int E = in_sizes[1] / 2;

    int nscan = (N + SCAN_B - 1) / SCAN_B;

    // graph preprocessing (shared by both layers)
    k_zero_counts<<<(N + 255) / 256, 256>>>(N);
    k_hist<<<(E + 255) / 256, 256>>>(ei, E);
    k_dinv<<<(N + 255) / 256, 256>>>(N);
    k_scan1<<<nscan, SCAN_B>>>(N);
    k_scan2<<<1, 128>>>(nscan, N);
    k_scan3<<<nscan, SCAN_B>>>(N);
    k_scatter<<<(E + 255) / 256, 256>>>(ei, E);

    int gemm_blocks = (N + TM - 1) / TM;
    dim3 gemm_threads(96, 2);
    int agg_blocks = (N * 32 + 255) / 256;

    // layer 1: x @ W1 -> g_h1 ; aggregate+PReLU -> g_h2
    k_gemm<<<gemm_blocks, gemm_threads>>>(x, W1, N, 0);
    k_agg<<<agg_blocks, 256>>>(b1, a1, out, N, 1, 0);
    // layer 2: g_h2 @ W2 -> g_h1 ; aggregate -> out
    k_gemm<<<gemm_blocks, gemm_threads>>>(x /*unused*/, W2, N, 1);
    k_agg<<<agg_blocks, 256>>>(b2, a1, out, N, 0, 1);
}